// round 15
// baseline (speedup 1.0000x reference)
#include <cuda_runtime.h>
#include <cuda_fp16.h>
#include <math.h>
#include <stdint.h>

// Problem constants
#define Bc 2
#define Nn 2048
#define DIMc 1024
#define Hh 16
#define HDc 64
#define Pp 2
#define M_ROWS (Bc * Nn)        // 4096
#define THREE_DIM (3 * DIMc)    // 3072

// Scratch (no cudaMalloc allowed)
__device__ float  g_qkv[M_ROWS * THREE_DIM];       // f32 qkv projection output
__device__ __half g_xh[M_ROWS * DIMc];             // fp16 x
__device__ __half g_wqkvt[THREE_DIM * DIMc];       // fp16 w_qkv^T  [n][k]
__device__ __half g_woutt[DIMc * DIMc];            // fp16 w_out^T  [n][k]
__device__ __half g_q[Bc * Hh * Nn * HDc];         // (b,h,n,d), q pre-scaled
__device__ __half g_k[Bc * Hh * Nn * HDc];
__device__ __half g_v[Bc * Hh * Nn * HDc];
__device__ __half g_attn[M_ROWS * DIMc];           // (b*n, h*HD)

// ---------------------------------------------------------------------------
// helpers
// ---------------------------------------------------------------------------
__device__ __forceinline__ float ex2(float x) {
    float r;
    asm("ex2.approx.ftz.f32 %0, %1;" : "=f"(r) : "f"(x));
    return r;
}
__device__ __forceinline__ void mma_f16(float d[4], const uint32_t a[4], const uint32_t b[2]) {
    asm volatile(
        "mma.sync.aligned.m16n8k16.row.col.f32.f16.f16.f32 "
        "{%0,%1,%2,%3}, {%4,%5,%6,%7}, {%8,%9}, {%0,%1,%2,%3};\n"
        : "+f"(d[0]), "+f"(d[1]), "+f"(d[2]), "+f"(d[3])
        : "r"(a[0]), "r"(a[1]), "r"(a[2]), "r"(a[3]), "r"(b[0]), "r"(b[1]));
}
__device__ __forceinline__ void ldm_x4(uint32_t r[4], uint32_t addr) {
    asm volatile("ldmatrix.sync.aligned.m8n8.x4.shared.b16 {%0,%1,%2,%3}, [%4];"
                 : "=r"(r[0]), "=r"(r[1]), "=r"(r[2]), "=r"(r[3]) : "r"(addr));
}
__device__ __forceinline__ void ldm_x2(uint32_t r[2], uint32_t addr) {
    asm volatile("ldmatrix.sync.aligned.m8n8.x2.shared.b16 {%0,%1}, [%2];"
                 : "=r"(r[0]), "=r"(r[1]) : "r"(addr));
}
__device__ __forceinline__ void ldm_x2t(uint32_t r[2], uint32_t addr) {
    asm volatile("ldmatrix.sync.aligned.m8n8.x2.trans.shared.b16 {%0,%1}, [%2];"
                 : "=r"(r[0]), "=r"(r[1]) : "r"(addr));
}
__device__ __forceinline__ uint32_t s2u(const void* p) {
    return (uint32_t)__cvta_generic_to_shared(p);
}

// ---------------------------------------------------------------------------
// f32 -> f16 convert (vectorized)
// ---------------------------------------------------------------------------
__global__ __launch_bounds__(256) void tohalf(
    const float4* __restrict__ src, uint2* __restrict__ dst, int n4)
{
    int i = blockIdx.x * blockDim.x + threadIdx.x;
    if (i < n4) {
        float4 v = src[i];
        __half2 h0 = __floats2half2_rn(v.x, v.y);
        __half2 h1 = __floats2half2_rn(v.z, v.w);
        uint2 o;
        o.x = *reinterpret_cast<uint32_t*>(&h0);
        o.y = *reinterpret_cast<uint32_t*>(&h1);
        dst[i] = o;
    }
}

// ---------------------------------------------------------------------------
// f32 [K][N] -> f16 [N][K] tiled transpose (coalesced both directions)
// ---------------------------------------------------------------------------
__global__ __launch_bounds__(256) void tohalf_T(
    const float* __restrict__ src, __half* __restrict__ dst, int K, int N)
{
    __shared__ float tile[32][33];
    int n0 = blockIdx.x * 32, k0 = blockIdx.y * 32;
    int tx = threadIdx.x & 31, ty = threadIdx.x >> 5;   // 32 x 8
#pragma unroll
    for (int i = ty; i < 32; i += 8)
        tile[i][tx] = src[(size_t)(k0 + i) * N + n0 + tx];
    __syncthreads();
#pragma unroll
    for (int i = ty; i < 32; i += 8)
        dst[(size_t)(n0 + i) * K + k0 + tx] = __float2half_rn(tile[tx][i]);
}

// ---------------------------------------------------------------------------
// fp16 tensor-core GEMM with PRE-TRANSPOSED B:
//   C[M,N](f32) = A[M,K](f16) @ Bt[N,K](f16)^T  (+bias f32)
// 256 threads = 8 warps (2x4), CTA tile 128x128, warp tile 64x32, BK=32.
// Both operands K-major; all fragments via non-transposed ldmatrix.
// ---------------------------------------------------------------------------
#define AP 40     // pitch (halfs): 32 + 8 (both As and Bs tiles)

__global__ __launch_bounds__(256) void gemm_f16t(
    const __half* __restrict__ A, const __half* __restrict__ Bt,
    float* __restrict__ C, int M, int N, int K,
    const float* __restrict__ bias)
{
    __shared__ __half As[2][128 * AP];   // [m][k]
    __shared__ __half Bs[2][128 * AP];   // [n][k]

    int tid = threadIdx.x, lane = tid & 31, warp = tid >> 5;
    int wm = (warp >> 2) * 64, wn = (warp & 3) * 32;
    int rb = blockIdx.y * 128, cb = blockIdx.x * 128;

    // loaders: row lr = tid>>1 (0..127), cols (tid&1)*16 .. +15 (2x uint4)
    int lr = tid >> 1, lc = (tid & 1) * 16;
    const __half* Ap = A  + (size_t)(rb + lr) * K + lc;
    const __half* Bp = Bt + (size_t)(cb + lr) * K + lc;

    uint4 ast[2], bst[2];
#pragma unroll
    for (int j = 0; j < 2; j++) {
        ast[j] = *(const uint4*)(Ap + j * 8);
        bst[j] = *(const uint4*)(Bp + j * 8);
    }
#pragma unroll
    for (int j = 0; j < 2; j++) {
        *(uint4*)&As[0][lr * AP + lc + j * 8] = ast[j];
        *(uint4*)&Bs[0][lr * AP + lc + j * 8] = bst[j];
    }
    {
        const __half* Ap2 = Ap + 32;
        const __half* Bp2 = Bp + 32;
#pragma unroll
        for (int j = 0; j < 2; j++) {
            ast[j] = *(const uint4*)(Ap2 + j * 8);
            bst[j] = *(const uint4*)(Bp2 + j * 8);
        }
    }
    __syncthreads();

    float acc[4][4][4];
#pragma unroll
    for (int mt = 0; mt < 4; mt++)
#pragma unroll
        for (int nt = 0; nt < 4; nt++)
#pragma unroll
            for (int i = 0; i < 4; i++) acc[mt][nt][i] = 0.f;

    int nk = K / 32;
    for (int kt = 0; kt < nk; kt++) {
        int s = kt & 1;
        if (kt + 1 < nk) {
            int s2 = s ^ 1;
#pragma unroll
            for (int j = 0; j < 2; j++) {
                *(uint4*)&As[s2][lr * AP + lc + j * 8] = ast[j];
                *(uint4*)&Bs[s2][lr * AP + lc + j * 8] = bst[j];
            }
        }
        if (kt + 2 < nk) {
            const __half* Ap2 = Ap + (kt + 2) * 32;
            const __half* Bp2 = Bp + (kt + 2) * 32;
#pragma unroll
            for (int j = 0; j < 2; j++) {
                ast[j] = *(const uint4*)(Ap2 + j * 8);
                bst[j] = *(const uint4*)(Bp2 + j * 8);
            }
        }
        uint32_t asb = s2u(&As[s][0]);
        uint32_t bsb = s2u(&Bs[s][0]);
#pragma unroll
        for (int ks = 0; ks < 2; ks++) {
            uint32_t afr[4][4], bfr[4][2];
#pragma unroll
            for (int mt = 0; mt < 4; mt++) {
                int row = wm + mt * 16 + (lane & 15);
                int col = ks * 16 + ((lane >> 4) << 3);
                ldm_x4(afr[mt], asb + (row * AP + col) * 2);
            }
#pragma unroll
            for (int nt = 0; nt < 4; nt++) {
                int row = wn + nt * 8 + (lane & 7);
                int col = ks * 16 + ((lane >> 3) & 1) * 8;
                ldm_x2(bfr[nt], bsb + (row * AP + col) * 2);
            }
#pragma unroll
            for (int mt = 0; mt < 4; mt++)
#pragma unroll
                for (int nt = 0; nt < 4; nt++)
                    mma_f16(acc[mt][nt], afr[mt], bfr[nt]);
        }
        __syncthreads();
    }

    // epilogue (f32)
#pragma unroll
    for (int mt = 0; mt < 4; mt++) {
        int r0 = rb + wm + mt * 16 + (lane >> 2);
#pragma unroll
        for (int nt = 0; nt < 4; nt++) {
            int c0 = cb + wn + nt * 8 + 2 * (lane & 3);
            float bx = 0.f, by = 0.f;
            if (bias) { bx = bias[c0]; by = bias[c0 + 1]; }
            float2 o0 = make_float2(acc[mt][nt][0] + bx, acc[mt][nt][1] + by);
            float2 o1 = make_float2(acc[mt][nt][2] + bx, acc[mt][nt][3] + by);
            *(float2*)&C[(size_t)r0 * N + c0] = o0;
            *(float2*)&C[(size_t)(r0 + 8) * N + c0] = o1;
        }
    }
}

// ---------------------------------------------------------------------------
// Axial RoPE + scatter, vectorized (R12 version, unchanged)
// ---------------------------------------------------------------------------
__global__ __launch_bounds__(256) void rope_scatter(
    const float* __restrict__ qkv, const float* __restrict__ pos,
    __half* __restrict__ qo, __half* __restrict__ ko, __half* __restrict__ vo)
{
    const float SC = 0.125f * 1.44269504f;
    __shared__ float cs[2][32], sn[2][32];
    int t = threadIdx.x;
    int bnl = t >> 7;
    int item = t & 127;
    int h = item >> 3, j = item & 7;
    int d0 = j * 4;

    for (int bn0 = blockIdx.x * 2; bn0 < M_ROWS; bn0 += gridDim.x * 2) {
        if (t < 64) {
            int bl = t >> 5, u = t & 31;
            int p = u >> 4, i = u & 15;
            float freq = expf(-(float)i * (9.210340371976184f / 16.f));
            float th = pos[(size_t)(bn0 + bl) * Pp + p] * freq;
            float s, c;
            sincosf(th, &s, &c);
            cs[bl][u] = c;
            sn[bl][u] = s;
        }
        __syncthreads();

        int bn = bn0 + bnl;
        int b = bn / Nn, n = bn % Nn;
        const float* base = qkv + (size_t)bn * THREE_DIM;
        size_t off = ((size_t)(b * Hh + h) * Nn + n) * HDc;

        float c0v = cs[bnl][d0],     s0v = sn[bnl][d0];
        float c1v = cs[bnl][d0 + 1], s1v = sn[bnl][d0 + 1];
        float c2v = cs[bnl][d0 + 2], s2v = sn[bnl][d0 + 2];
        float c3v = cs[bnl][d0 + 3], s3v = sn[bnl][d0 + 3];

        {
            float4 x1 = *(const float4*)(base + h * HDc + d0);
            float4 x2 = *(const float4*)(base + h * HDc + 32 + d0);
            __half2 lo0 = __floats2half2_rn((x1.x * c0v - x2.x * s0v) * SC,
                                            (x1.y * c1v - x2.y * s1v) * SC);
            __half2 lo1 = __floats2half2_rn((x1.z * c2v - x2.z * s2v) * SC,
                                            (x1.w * c3v - x2.w * s3v) * SC);
            __half2 hi0 = __floats2half2_rn((x1.x * s0v + x2.x * c0v) * SC,
                                            (x1.y * s1v + x2.y * c1v) * SC);
            __half2 hi1 = __floats2half2_rn((x1.z * s2v + x2.z * c2v) * SC,
                                            (x1.w * s3v + x2.w * c3v) * SC);
            uint2 olo, ohi;
            olo.x = *(uint32_t*)&lo0; olo.y = *(uint32_t*)&lo1;
            ohi.x = *(uint32_t*)&hi0; ohi.y = *(uint32_t*)&hi1;
            *(uint2*)(qo + off + d0) = olo;
            *(uint2*)(qo + off + 32 + d0) = ohi;
        }
        {
            float4 x1 = *(const float4*)(base + DIMc + h * HDc + d0);
            float4 x2 = *(const float4*)(base + DIMc + h * HDc + 32 + d0);
            __half2 lo0 = __floats2half2_rn(x1.x * c0v - x2.x * s0v,
                                            x1.y * c1v - x2.y * s1v);
            __half2 lo1 = __floats2half2_rn(x1.z * c2v - x2.z * s2v,
                                            x1.w * c3v - x2.w * s3v);
            __half2 hi0 = __floats2half2_rn(x1.x * s0v + x2.x * c0v,
                                            x1.y * s1v + x2.y * c1v);
            __half2 hi1 = __floats2half2_rn(x1.z * s2v + x2.z * c2v,
                                            x1.w * s3v + x2.w * c3v);
            uint2 olo, ohi;
            olo.x = *(uint32_t*)&lo0; olo.y = *(uint32_t*)&lo1;
            ohi.x = *(uint32_t*)&hi0; ohi.y = *(uint32_t*)&hi1;
            *(uint2*)(ko + off + d0) = olo;
            *(uint2*)(ko + off + 32 + d0) = ohi;
        }
        {
            float4 x1 = *(const float4*)(base + 2 * DIMc + h * HDc + d0);
            float4 x2 = *(const float4*)(base + 2 * DIMc + h * HDc + 32 + d0);
            __half2 lo0 = __floats2half2_rn(x1.x, x1.y);
            __half2 lo1 = __floats2half2_rn(x1.z, x1.w);
            __half2 hi0 = __floats2half2_rn(x2.x, x2.y);
            __half2 hi1 = __floats2half2_rn(x2.z, x2.w);
            uint2 olo, ohi;
            olo.x = *(uint32_t*)&lo0; olo.y = *(uint32_t*)&lo1;
            ohi.x = *(uint32_t*)&hi0; ohi.y = *(uint32_t*)&hi1;
            *(uint2*)(vo + off + d0) = olo;
            *(uint2*)(vo + off + 32 + d0) = ohi;
        }
        __syncthreads();
    }
}

// ---------------------------------------------------------------------------
// Flash attention (R13 version, unchanged): 256 threads, 128q x 64k tiles.
// ---------------------------------------------------------------------------
#define QP 72   // half pitch: 64 + 8

__global__ __launch_bounds__(256) void flash_f16(
    const __half* __restrict__ Q, const __half* __restrict__ K,
    const __half* __restrict__ V, __half* __restrict__ O)
{
    __shared__ __half Qs[128 * QP];    // reused as Ps after Q frag hoist
    __shared__ __half Ks[64 * QP];
    __shared__ __half Vs[64 * QP];
    __shared__ float mrow[128], lrow[128], rmax[256], rsum[256];

    int tid = threadIdx.x, lane = tid & 31, warp = tid >> 5;
    int wq = warp >> 1, wk = warp & 1;
    int wm = wq * 32, wn = wk * 32;
    int bh = blockIdx.y, qt = blockIdx.x;
    int b = bh >> 4, h = bh & 15;

    const __half* Qb = Q + ((size_t)bh * Nn + qt * 128) * HDc;
    const __half* Kb = K + (size_t)bh * Nn * HDc;
    const __half* Vb = V + (size_t)bh * Nn * HDc;

    int lr = tid >> 1, lc = (tid & 1) * 32;
    {
        const __half* qg = Qb + (size_t)lr * HDc + lc;
#pragma unroll
        for (int j = 0; j < 4; j++)
            *(uint4*)&Qs[lr * QP + lc + j * 8] = *(const uint4*)(qg + j * 8);
    }
    if (tid < 128) { mrow[tid] = -1e30f; lrow[tid] = 0.f; }
    __syncthreads();

    uint32_t qfr[4][2][4];
    {
        uint32_t qsb = s2u(&Qs[0]);
#pragma unroll
        for (int ks = 0; ks < 4; ks++)
#pragma unroll
            for (int mt = 0; mt < 2; mt++) {
                int row = wm + mt * 16 + (lane & 15);
                int col = ks * 16 + ((lane >> 4) << 3);
                ldm_x4(qfr[ks][mt], qsb + (row * QP + col) * 2);
            }
    }
    __half* Ps = Qs;

    float accO[2][4][4];
#pragma unroll
    for (int mt = 0; mt < 2; mt++)
#pragma unroll
        for (int nt = 0; nt < 4; nt++)
#pragma unroll
            for (int i = 0; i < 4; i++) accO[mt][nt][i] = 0.f;

    uint32_t ksb = s2u(&Ks[0]);
    uint32_t vsb = s2u(&Vs[0]);
    uint32_t psb = s2u(&Ps[0]);

    int kr = tid >> 2, kc = (tid & 3) * 16;

    for (int kt = 0; kt < Nn / 64; kt++) {
        {
            const __half* kg = Kb + ((size_t)(kt * 64 + kr)) * HDc + kc;
            const __half* vg = Vb + ((size_t)(kt * 64 + kr)) * HDc + kc;
#pragma unroll
            for (int j = 0; j < 2; j++) {
                *(uint4*)&Ks[kr * QP + kc + j * 8] = *(const uint4*)(kg + j * 8);
                *(uint4*)&Vs[kr * QP + kc + j * 8] = *(const uint4*)(vg + j * 8);
            }
        }
        __syncthreads();

        float s[2][4][4];
#pragma unroll
        for (int mt = 0; mt < 2; mt++)
#pragma unroll
            for (int nt = 0; nt < 4; nt++)
#pragma unroll
                for (int i = 0; i < 4; i++) s[mt][nt][i] = 0.f;
#pragma unroll
        for (int ks = 0; ks < 4; ks++) {
#pragma unroll
            for (int nt = 0; nt < 4; nt++) {
                int row = wn + nt * 8 + (lane & 7);
                int col = ks * 16 + ((lane >> 3) & 1) * 8;
                uint32_t bfr[2];
                ldm_x2(bfr, ksb + (row * QP + col) * 2);
#pragma unroll
                for (int mt = 0; mt < 2; mt++)
                    mma_f16(s[mt][nt], qfr[ks][mt], bfr);
            }
        }

        float mxa[2], mxb[2];
#pragma unroll
        for (int mt = 0; mt < 2; mt++) {
            float ma = -1e30f, mb = -1e30f;
#pragma unroll
            for (int nt = 0; nt < 4; nt++) {
                ma = fmaxf(ma, fmaxf(s[mt][nt][0], s[mt][nt][1]));
                mb = fmaxf(mb, fmaxf(s[mt][nt][2], s[mt][nt][3]));
            }
            ma = fmaxf(ma, __shfl_xor_sync(0xffffffffu, ma, 1));
            ma = fmaxf(ma, __shfl_xor_sync(0xffffffffu, ma, 2));
            mb = fmaxf(mb, __shfl_xor_sync(0xffffffffu, mb, 1));
            mb = fmaxf(mb, __shfl_xor_sync(0xffffffffu, mb, 2));
            mxa[mt] = ma; mxb[mt] = mb;
        }
        if ((lane & 3) == 0) {
#pragma unroll
            for (int mt = 0; mt < 2; mt++) {
                int rA = wm + mt * 16 + (lane >> 2);
                rmax[wk * 128 + rA] = mxa[mt];
                rmax[wk * 128 + rA + 8] = mxb[mt];
            }
        }
        __syncthreads();

#pragma unroll
        for (int mt = 0; mt < 2; mt++) {
            int rA = wm + mt * 16 + (lane >> 2);
            int rB = rA + 8;
            float moA = mrow[rA];
            float moB = mrow[rB];
            float mnA = fmaxf(moA, fmaxf(rmax[rA], rmax[128 + rA]));
            float mnB = fmaxf(moB, fmaxf(rmax[rB], rmax[128 + rB]));
            float fA = ex2(moA - mnA);
            float fB = ex2(moB - mnB);
            float sa = 0.f, sb = 0.f;
#pragma unroll
            for (int nt = 0; nt < 4; nt++) {
                float p0 = ex2(s[mt][nt][0] - mnA);
                float p1 = ex2(s[mt][nt][1] - mnA);
                float p2 = ex2(s[mt][nt][2] - mnB);
                float p3 = ex2(s[mt][nt][3] - mnB);
                sa += p0 + p1;
                sb += p2 + p3;
                accO[mt][nt][0] *= fA;
                accO[mt][nt][1] *= fA;
                accO[mt][nt][2] *= fB;
                accO[mt][nt][3] *= fB;
                int c0 = wn + nt * 8 + 2 * (lane & 3);
                *(__half2*)&Ps[rA * QP + c0] = __floats2half2_rn(p0, p1);
                *(__half2*)&Ps[rB * QP + c0] = __floats2half2_rn(p2, p3);
            }
            sa += __shfl_xor_sync(0xffffffffu, sa, 1);
            sa += __shfl_xor_sync(0xffffffffu, sa, 2);
            sb += __shfl_xor_sync(0xffffffffu, sb, 1);
            sb += __shfl_xor_sync(0xffffffffu, sb, 2);
            if ((lane & 3) == 0) {
                rsum[wk * 128 + rA] = sa;
                rsum[wk * 128 + rB] = sb;
            }
        }
        __syncthreads();

        if (tid < 128) {
            int r = tid;
            float mo = mrow[r];
            float mn = fmaxf(mo, fmaxf(rmax[r], rmax[128 + r]));
            lrow[r] = lrow[r] * ex2(mo - mn) + rsum[r] + rsum[128 + r];
            mrow[r] = mn;
        }

#pragma unroll
        for (int ks = 0; ks < 4; ks++) {
            uint32_t afr[2][4];
#pragma unroll
            for (int mt = 0; mt < 2; mt++) {
                int row = wm + mt * 16 + (lane & 15);
                int col = ks * 16 + ((lane >> 4) << 3);
                ldm_x4(afr[mt], psb + (row * QP + col) * 2);
            }
#pragma unroll
            for (int nt = 0; nt < 4; nt++) {
                int row = ks * 16 + (lane & 15);
                int col = wn + nt * 8;
                uint32_t bfr[2];
                ldm_x2t(bfr, vsb + (row * QP + col) * 2);
#pragma unroll
                for (int mt = 0; mt < 2; mt++)
                    mma_f16(accO[mt][nt], afr[mt], bfr);
            }
        }
        __syncthreads();
    }

#pragma unroll
    for (int mt = 0; mt < 2; mt++) {
        int rA = wm + mt * 16 + (lane >> 2);
        int rB = rA + 8;
        float ia = 1.f / lrow[rA];
        float ib = 1.f / lrow[rB];
        size_t rowA = ((size_t)(b * Nn + qt * 128 + rA)) * DIMc + h * HDc;
        size_t rowB = ((size_t)(b * Nn + qt * 128 + rB)) * DIMc + h * HDc;
#pragma unroll
        for (int nt = 0; nt < 4; nt++) {
            int c0 = wn + nt * 8 + 2 * (lane & 3);
            *(__half2*)&O[rowA + c0] = __floats2half2_rn(accO[mt][nt][0] * ia, accO[mt][nt][1] * ia);
            *(__half2*)&O[rowB + c0] = __floats2half2_rn(accO[mt][nt][2] * ib, accO[mt][nt][3] * ib);
        }
    }
}

// ---------------------------------------------------------------------------
extern "C" void kernel_launch(void* const* d_in, const int* in_sizes, int n_in,
                              void* d_out, int out_size)
{
    (void)in_sizes; (void)n_in; (void)out_size;
    const float* x     = (const float*)d_in[0];
    const float* pos   = (const float*)d_in[1];
    const float* w_qkv = (const float*)d_in[2];
    const float* w_out = (const float*)d_in[3];
    const float* b_out = (const float*)d_in[4];
    float* out = (float*)d_out;

    float* qkv;
    __half *xh, *wqkvt, *woutt, *q, *k, *v, *attn;
    cudaGetSymbolAddress((void**)&qkv,   g_qkv);
    cudaGetSymbolAddress((void**)&xh,    g_xh);
    cudaGetSymbolAddress((void**)&wqkvt, g_wqkvt);
    cudaGetSymbolAddress((void**)&woutt, g_woutt);
    cudaGetSymbolAddress((void**)&q,     g_q);
    cudaGetSymbolAddress((void**)&k,     g_k);
    cudaGetSymbolAddress((void**)&v,     g_v);
    cudaGetSymbolAddress((void**)&attn,  g_attn);

    // 0) convert x to fp16; transpose+convert weights to [n][k] fp16
    {
        int n4x = M_ROWS * DIMc / 4;
        tohalf<<<(n4x + 255) / 256, 256>>>((const float4*)x, (uint2*)xh, n4x);
        dim3 g1(THREE_DIM / 32, DIMc / 32);
        tohalf_T<<<g1, 256>>>(w_qkv, wqkvt, DIMc, THREE_DIM);
        dim3 g2(DIMc / 32, DIMc / 32);
        tohalf_T<<<g2, 256>>>(w_out, woutt, DIMc, DIMc);
    }
    // 1) QKV projection (both operands K-major)
    {
        dim3 grid(THREE_DIM / 128, M_ROWS / 128);
        gemm_f16t<<<grid, 256>>>(xh, wqkvt, qkv, M_ROWS, THREE_DIM, DIMc, nullptr);
    }
    // 2) RoPE + scatter
    rope_scatter<<<512, 256>>>(qkv, pos, q, k, v);
    // 3) Flash attention (128-query tiles)
    {
        dim3 grid(Nn / 128, Bc * Hh);
        flash_f16<<<grid, 256>>>(q, k, v, attn);
    }
    // 4) Output projection + bias
    {
        dim3 grid(DIMc / 128, M_ROWS / 128);
        gemm_f16t<<<grid, 256>>>(attn, woutt, out, M_ROWS, DIMc, DIMc, b_out);
    }
}

// round 16
// speedup vs baseline: 1.0865x; 1.0865x over previous
#include <cuda_runtime.h>
#include <cuda_fp16.h>
#include <math.h>
#include <stdint.h>

// Problem constants
#define Bc 2
#define Nn 2048
#define DIMc 1024
#define Hh 16
#define HDc 64
#define Pp 2
#define M_ROWS (Bc * Nn)        // 4096
#define THREE_DIM (3 * DIMc)    // 3072

// Scratch (no cudaMalloc allowed)
__device__ float  g_qkv[M_ROWS * THREE_DIM];       // f32 qkv projection output
__device__ __half g_xh[M_ROWS * DIMc];             // fp16 x
__device__ __half g_wqkvh[DIMc * THREE_DIM];       // fp16 w_qkv
__device__ __half g_wouth[DIMc * DIMc];            // fp16 w_out
__device__ __half g_q[Bc * Hh * Nn * HDc];         // (b,h,n,d), q pre-scaled
__device__ __half g_k[Bc * Hh * Nn * HDc];
__device__ __half g_v[Bc * Hh * Nn * HDc];
__device__ __half g_attn[M_ROWS * DIMc];           // (b*n, h*HD)

// ---------------------------------------------------------------------------
// helpers
// ---------------------------------------------------------------------------
__device__ __forceinline__ float ex2(float x) {
    float r;
    asm("ex2.approx.ftz.f32 %0, %1;" : "=f"(r) : "f"(x));
    return r;
}
__device__ __forceinline__ void mma_f16(float d[4], const uint32_t a[4], const uint32_t b[2]) {
    asm volatile(
        "mma.sync.aligned.m16n8k16.row.col.f32.f16.f16.f32 "
        "{%0,%1,%2,%3}, {%4,%5,%6,%7}, {%8,%9}, {%0,%1,%2,%3};\n"
        : "+f"(d[0]), "+f"(d[1]), "+f"(d[2]), "+f"(d[3])
        : "r"(a[0]), "r"(a[1]), "r"(a[2]), "r"(a[3]), "r"(b[0]), "r"(b[1]));
}
__device__ __forceinline__ void ldm_x4(uint32_t r[4], uint32_t addr) {
    asm volatile("ldmatrix.sync.aligned.m8n8.x4.shared.b16 {%0,%1,%2,%3}, [%4];"
                 : "=r"(r[0]), "=r"(r[1]), "=r"(r[2]), "=r"(r[3]) : "r"(addr));
}
__device__ __forceinline__ void ldm_x2(uint32_t r[2], uint32_t addr) {
    asm volatile("ldmatrix.sync.aligned.m8n8.x2.shared.b16 {%0,%1}, [%2];"
                 : "=r"(r[0]), "=r"(r[1]) : "r"(addr));
}
__device__ __forceinline__ void ldm_x2t(uint32_t r[2], uint32_t addr) {
    asm volatile("ldmatrix.sync.aligned.m8n8.x2.trans.shared.b16 {%0,%1}, [%2];"
                 : "=r"(r[0]), "=r"(r[1]) : "r"(addr));
}
__device__ __forceinline__ uint32_t s2u(const void* p) {
    return (uint32_t)__cvta_generic_to_shared(p);
}

// ---------------------------------------------------------------------------
// f32 -> f16 convert (vectorized)
// ---------------------------------------------------------------------------
__global__ __launch_bounds__(256) void tohalf(
    const float4* __restrict__ src, uint2* __restrict__ dst, int n4)
{
    int i = blockIdx.x * blockDim.x + threadIdx.x;
    if (i < n4) {
        float4 v = src[i];
        __half2 h0 = __floats2half2_rn(v.x, v.y);
        __half2 h1 = __floats2half2_rn(v.z, v.w);
        uint2 o;
        o.x = *reinterpret_cast<uint32_t*>(&h0);
        o.y = *reinterpret_cast<uint32_t*>(&h1);
        dst[i] = o;
    }
}

// ---------------------------------------------------------------------------
// fp16 tensor-core GEMM (R12/R13 version, EXACT): 256 threads = 8 warps
// (2x4), CTA 128x128, warp 64x32, BK=32, single barrier per k-tile.
// ---------------------------------------------------------------------------
#define AP 40     // As pitch (halfs): 32 + 8
#define BP 136    // Bs pitch (halfs): 128 + 8

__global__ __launch_bounds__(256) void gemm_f16(
    const __half* __restrict__ A, const __half* __restrict__ B,
    float* __restrict__ C, int M, int N, int K,
    const float* __restrict__ bias)
{
    __shared__ __half As[2][128 * AP];   // [m][k]
    __shared__ __half Bs[2][32 * BP];    // [k][n]

    int tid = threadIdx.x, lane = tid & 31, warp = tid >> 5;
    int wm = (warp >> 2) * 64, wn = (warp & 3) * 32;
    int rb = blockIdx.y * 128, cb = blockIdx.x * 128;

    int ar = tid >> 1, ac = (tid & 1) * 16;
    int br = tid >> 3, bc = (tid & 7) * 16;
    const __half* Ap = A + (size_t)(rb + ar) * K + ac;
    const __half* Bp = B + (size_t)br * N + cb + bc;

    uint4 ast[2], bst[2];
#pragma unroll
    for (int j = 0; j < 2; j++) {
        ast[j] = *(const uint4*)(Ap + j * 8);
        bst[j] = *(const uint4*)(Bp + j * 8);
    }
#pragma unroll
    for (int j = 0; j < 2; j++) {
        *(uint4*)&As[0][ar * AP + ac + j * 8] = ast[j];
        *(uint4*)&Bs[0][br * BP + bc + j * 8] = bst[j];
    }
    {
        const __half* Ap2 = Ap + 32;
        const __half* Bp2 = Bp + (size_t)32 * N;
#pragma unroll
        for (int j = 0; j < 2; j++) {
            ast[j] = *(const uint4*)(Ap2 + j * 8);
            bst[j] = *(const uint4*)(Bp2 + j * 8);
        }
    }
    __syncthreads();

    float acc[4][4][4];
#pragma unroll
    for (int mt = 0; mt < 4; mt++)
#pragma unroll
        for (int nt = 0; nt < 4; nt++)
#pragma unroll
            for (int i = 0; i < 4; i++) acc[mt][nt][i] = 0.f;

    int nk = K / 32;
    for (int kt = 0; kt < nk; kt++) {
        int s = kt & 1;
        if (kt + 1 < nk) {
            int s2 = s ^ 1;
#pragma unroll
            for (int j = 0; j < 2; j++) {
                *(uint4*)&As[s2][ar * AP + ac + j * 8] = ast[j];
                *(uint4*)&Bs[s2][br * BP + bc + j * 8] = bst[j];
            }
        }
        if (kt + 2 < nk) {
            const __half* Ap2 = Ap + (kt + 2) * 32;
            const __half* Bp2 = Bp + (size_t)(kt + 2) * 32 * N;
#pragma unroll
            for (int j = 0; j < 2; j++) {
                ast[j] = *(const uint4*)(Ap2 + j * 8);
                bst[j] = *(const uint4*)(Bp2 + j * 8);
            }
        }
        uint32_t asb = s2u(&As[s][0]);
        uint32_t bsb = s2u(&Bs[s][0]);
#pragma unroll
        for (int ks = 0; ks < 2; ks++) {
            uint32_t afr[4][4], bfr[4][2];
#pragma unroll
            for (int mt = 0; mt < 4; mt++) {
                int row = wm + mt * 16 + (lane & 15);
                int col = ks * 16 + ((lane >> 4) << 3);
                ldm_x4(afr[mt], asb + (row * AP + col) * 2);
            }
#pragma unroll
            for (int nt = 0; nt < 4; nt++) {
                int row = ks * 16 + (lane & 15);
                int col = wn + nt * 8;
                ldm_x2t(bfr[nt], bsb + (row * BP + col) * 2);
            }
#pragma unroll
            for (int mt = 0; mt < 4; mt++)
#pragma unroll
                for (int nt = 0; nt < 4; nt++)
                    mma_f16(acc[mt][nt], afr[mt], bfr[nt]);
        }
        __syncthreads();
    }

#pragma unroll
    for (int mt = 0; mt < 4; mt++) {
        int r0 = rb + wm + mt * 16 + (lane >> 2);
#pragma unroll
        for (int nt = 0; nt < 4; nt++) {
            int c0 = cb + wn + nt * 8 + 2 * (lane & 3);
            float bx = 0.f, by = 0.f;
            if (bias) { bx = bias[c0]; by = bias[c0 + 1]; }
            float2 o0 = make_float2(acc[mt][nt][0] + bx, acc[mt][nt][1] + by);
            float2 o1 = make_float2(acc[mt][nt][2] + bx, acc[mt][nt][3] + by);
            *(float2*)&C[(size_t)r0 * N + c0] = o0;
            *(float2*)&C[(size_t)(r0 + 8) * N + c0] = o1;
        }
    }
}

// ---------------------------------------------------------------------------
// Axial RoPE + scatter, vectorized (R12 version, unchanged)
// ---------------------------------------------------------------------------
__global__ __launch_bounds__(256) void rope_scatter(
    const float* __restrict__ qkv, const float* __restrict__ pos,
    __half* __restrict__ qo, __half* __restrict__ ko, __half* __restrict__ vo)
{
    const float SC = 0.125f * 1.44269504f;
    __shared__ float cs[2][32], sn[2][32];
    int t = threadIdx.x;
    int bnl = t >> 7;
    int item = t & 127;
    int h = item >> 3, j = item & 7;
    int d0 = j * 4;

    for (int bn0 = blockIdx.x * 2; bn0 < M_ROWS; bn0 += gridDim.x * 2) {
        if (t < 64) {
            int bl = t >> 5, u = t & 31;
            int p = u >> 4, i = u & 15;
            float freq = expf(-(float)i * (9.210340371976184f / 16.f));
            float th = pos[(size_t)(bn0 + bl) * Pp + p] * freq;
            float s, c;
            sincosf(th, &s, &c);
            cs[bl][u] = c;
            sn[bl][u] = s;
        }
        __syncthreads();

        int bn = bn0 + bnl;
        int b = bn / Nn, n = bn % Nn;
        const float* base = qkv + (size_t)bn * THREE_DIM;
        size_t off = ((size_t)(b * Hh + h) * Nn + n) * HDc;

        float c0v = cs[bnl][d0],     s0v = sn[bnl][d0];
        float c1v = cs[bnl][d0 + 1], s1v = sn[bnl][d0 + 1];
        float c2v = cs[bnl][d0 + 2], s2v = sn[bnl][d0 + 2];
        float c3v = cs[bnl][d0 + 3], s3v = sn[bnl][d0 + 3];

        {
            float4 x1 = *(const float4*)(base + h * HDc + d0);
            float4 x2 = *(const float4*)(base + h * HDc + 32 + d0);
            __half2 lo0 = __floats2half2_rn((x1.x * c0v - x2.x * s0v) * SC,
                                            (x1.y * c1v - x2.y * s1v) * SC);
            __half2 lo1 = __floats2half2_rn((x1.z * c2v - x2.z * s2v) * SC,
                                            (x1.w * c3v - x2.w * s3v) * SC);
            __half2 hi0 = __floats2half2_rn((x1.x * s0v + x2.x * c0v) * SC,
                                            (x1.y * s1v + x2.y * c1v) * SC);
            __half2 hi1 = __floats2half2_rn((x1.z * s2v + x2.z * c2v) * SC,
                                            (x1.w * s3v + x2.w * c3v) * SC);
            uint2 olo, ohi;
            olo.x = *(uint32_t*)&lo0; olo.y = *(uint32_t*)&lo1;
            ohi.x = *(uint32_t*)&hi0; ohi.y = *(uint32_t*)&hi1;
            *(uint2*)(qo + off + d0) = olo;
            *(uint2*)(qo + off + 32 + d0) = ohi;
        }
        {
            float4 x1 = *(const float4*)(base + DIMc + h * HDc + d0);
            float4 x2 = *(const float4*)(base + DIMc + h * HDc + 32 + d0);
            __half2 lo0 = __floats2half2_rn(x1.x * c0v - x2.x * s0v,
                                            x1.y * c1v - x2.y * s1v);
            __half2 lo1 = __floats2half2_rn(x1.z * c2v - x2.z * s2v,
                                            x1.w * c3v - x2.w * s3v);
            __half2 hi0 = __floats2half2_rn(x1.x * s0v + x2.x * c0v,
                                            x1.y * s1v + x2.y * c1v);
            __half2 hi1 = __floats2half2_rn(x1.z * s2v + x2.z * c2v,
                                            x1.w * s3v + x2.w * c3v);
            uint2 olo, ohi;
            olo.x = *(uint32_t*)&lo0; olo.y = *(uint32_t*)&lo1;
            ohi.x = *(uint32_t*)&hi0; ohi.y = *(uint32_t*)&hi1;
            *(uint2*)(ko + off + d0) = olo;
            *(uint2*)(ko + off + 32 + d0) = ohi;
        }
        {
            float4 x1 = *(const float4*)(base + 2 * DIMc + h * HDc + d0);
            float4 x2 = *(const float4*)(base + 2 * DIMc + h * HDc + 32 + d0);
            __half2 lo0 = __floats2half2_rn(x1.x, x1.y);
            __half2 lo1 = __floats2half2_rn(x1.z, x1.w);
            __half2 hi0 = __floats2half2_rn(x2.x, x2.y);
            __half2 hi1 = __floats2half2_rn(x2.z, x2.w);
            uint2 olo, ohi;
            olo.x = *(uint32_t*)&lo0; olo.y = *(uint32_t*)&lo1;
            ohi.x = *(uint32_t*)&hi0; ohi.y = *(uint32_t*)&hi1;
            *(uint2*)(vo + off + d0) = olo;
            *(uint2*)(vo + off + 32 + d0) = ohi;
        }
        __syncthreads();
    }
}

// ---------------------------------------------------------------------------
// Flash attention, fp16 mma. 256 threads = 8 warps; 128q x 64k tile.
// Each warp owns a 16-query strip x FULL 64 keys -> softmax state entirely
// in registers, P rows warp-private (Ps aliases Qs), 2 barriers per tile.
// ---------------------------------------------------------------------------
#define QP 72   // half pitch: 64 + 8

__global__ __launch_bounds__(256) void flash_f16(
    const __half* __restrict__ Q, const __half* __restrict__ K,
    const __half* __restrict__ V, __half* __restrict__ O)
{
    __shared__ __half Qs[128 * QP];    // reused as Ps after Q frag hoist
    __shared__ __half Ks[64 * QP];
    __shared__ __half Vs[64 * QP];

    int tid = threadIdx.x, lane = tid & 31, warp = tid >> 5;
    int wm = warp * 16;                 // 16-query strip
    int bh = blockIdx.y, qt = blockIdx.x;
    int b = bh >> 4, h = bh & 15;

    const __half* Qb = Q + ((size_t)bh * Nn + qt * 128) * HDc;
    const __half* Kb = K + (size_t)bh * Nn * HDc;
    const __half* Vb = V + (size_t)bh * Nn * HDc;

    // load Q tile (128x64): thread -> row tid>>1, cols (tid&1)*32
    int lr = tid >> 1, lc = (tid & 1) * 32;
    {
        const __half* qg = Qb + (size_t)lr * HDc + lc;
#pragma unroll
        for (int j = 0; j < 4; j++)
            *(uint4*)&Qs[lr * QP + lc + j * 8] = *(const uint4*)(qg + j * 8);
    }
    __syncthreads();

    // hoist Q fragments (16 rows x 64 d per warp)
    uint32_t qfr[4][4];
    {
        uint32_t qsb = s2u(&Qs[0]);
#pragma unroll
        for (int ks = 0; ks < 4; ks++) {
            int row = wm + (lane & 15);
            int col = ks * 16 + ((lane >> 4) << 3);
            ldm_x4(qfr[ks], qsb + (row * QP + col) * 2);
        }
    }
    __half* Ps = Qs;

    float accO[8][4];
#pragma unroll
    for (int nt = 0; nt < 8; nt++)
#pragma unroll
        for (int i = 0; i < 4; i++) accO[nt][i] = 0.f;
    float mA = -1e30f, mB = -1e30f, lA = 0.f, lB = 0.f;

    uint32_t ksb = s2u(&Ks[0]);
    uint32_t vsb = s2u(&Vs[0]);
    uint32_t psb = s2u(&Ps[0]);

    // K/V loader: thread -> row tid>>2 (0..63), cols (tid&3)*16
    int kr = tid >> 2, kc = (tid & 3) * 16;
    int rA = wm + (lane >> 2), rB = rA + 8;

    for (int kt = 0; kt < Nn / 64; kt++) {
        {
            const __half* kg = Kb + ((size_t)(kt * 64 + kr)) * HDc + kc;
            const __half* vg = Vb + ((size_t)(kt * 64 + kr)) * HDc + kc;
#pragma unroll
            for (int j = 0; j < 2; j++) {
                *(uint4*)&Ks[kr * QP + kc + j * 8] = *(const uint4*)(kg + j * 8);
                *(uint4*)&Vs[kr * QP + kc + j * 8] = *(const uint4*)(vg + j * 8);
            }
        }
        __syncthreads();   // (1) tiles ready

        // S = Q @ K^T  (warp: 16q x 64k)
        float s[8][4];
#pragma unroll
        for (int nt = 0; nt < 8; nt++)
#pragma unroll
            for (int i = 0; i < 4; i++) s[nt][i] = 0.f;
#pragma unroll
        for (int ks = 0; ks < 4; ks++) {
#pragma unroll
            for (int nt = 0; nt < 8; nt++) {
                int row = nt * 8 + (lane & 7);
                int col = ks * 16 + ((lane >> 3) & 1) * 8;
                uint32_t bfr[2];
                ldm_x2(bfr, ksb + (row * QP + col) * 2);
                mma_f16(s[nt], qfr[ks], bfr);
            }
        }

        // warp-local row max over all 64 keys
        float ma = -1e30f, mb = -1e30f;
#pragma unroll
        for (int nt = 0; nt < 8; nt++) {
            ma = fmaxf(ma, fmaxf(s[nt][0], s[nt][1]));
            mb = fmaxf(mb, fmaxf(s[nt][2], s[nt][3]));
        }
        ma = fmaxf(ma, __shfl_xor_sync(0xffffffffu, ma, 1));
        ma = fmaxf(ma, __shfl_xor_sync(0xffffffffu, ma, 2));
        mb = fmaxf(mb, __shfl_xor_sync(0xffffffffu, mb, 1));
        mb = fmaxf(mb, __shfl_xor_sync(0xffffffffu, mb, 2));

        float mnA = fmaxf(mA, ma), mnB = fmaxf(mB, mb);
        float fA = ex2(mA - mnA), fB = ex2(mB - mnB);

        // exponentiate, partial sums, store P (warp-private rows)
        float sa = 0.f, sb = 0.f;
#pragma unroll
        for (int nt = 0; nt < 8; nt++) {
            float p0 = ex2(s[nt][0] - mnA);
            float p1 = ex2(s[nt][1] - mnA);
            float p2 = ex2(s[nt][2] - mnB);
            float p3 = ex2(s[nt][3] - mnB);
            sa += p0 + p1;
            sb += p2 + p3;
            int c0 = nt * 8 + 2 * (lane & 3);
            *(__half2*)&Ps[rA * QP + c0] = __floats2half2_rn(p0, p1);
            *(__half2*)&Ps[rB * QP + c0] = __floats2half2_rn(p2, p3);
        }
        sa += __shfl_xor_sync(0xffffffffu, sa, 1);
        sa += __shfl_xor_sync(0xffffffffu, sa, 2);
        sb += __shfl_xor_sync(0xffffffffu, sb, 1);
        sb += __shfl_xor_sync(0xffffffffu, sb, 2);
        lA = lA * fA + sa;
        lB = lB * fB + sb;
        mA = mnA;
        mB = mnB;

        // rescale accumulators
#pragma unroll
        for (int nt = 0; nt < 8; nt++) {
            accO[nt][0] *= fA;
            accO[nt][1] *= fA;
            accO[nt][2] *= fB;
            accO[nt][3] *= fB;
        }
        __syncwarp();      // order P stores before own-warp ldmatrix

        // O += P @ V  (warp: 16q x 64d, full 64 k)
#pragma unroll
        for (int ks = 0; ks < 4; ks++) {
            uint32_t afr[4];
            {
                int row = wm + (lane & 15);
                int col = ks * 16 + ((lane >> 4) << 3);
                ldm_x4(afr, psb + (row * QP + col) * 2);
            }
#pragma unroll
            for (int nt = 0; nt < 8; nt++) {
                int row = ks * 16 + (lane & 15);
                int col = nt * 8;
                uint32_t bfr[2];
                ldm_x2t(bfr, vsb + (row * QP + col) * 2);
                mma_f16(accO[nt], afr, bfr);
            }
        }
        __syncthreads();   // (2) all K/V reads done before next overwrite
    }

    // epilogue: normalize, store fp16 to (b*n, h*HD)
    float ia = 1.f / lA, ib = 1.f / lB;
    size_t rowA = ((size_t)(b * Nn + qt * 128 + rA)) * DIMc + h * HDc;
    size_t rowB = ((size_t)(b * Nn + qt * 128 + rB)) * DIMc + h * HDc;
#pragma unroll
    for (int nt = 0; nt < 8; nt++) {
        int c0 = nt * 8 + 2 * (lane & 3);
        *(__half2*)&O[rowA + c0] = __floats2half2_rn(accO[nt][0] * ia, accO[nt][1] * ia);
        *(__half2*)&O[rowB + c0] = __floats2half2_rn(accO[nt][2] * ib, accO[nt][3] * ib);
    }
}

// ---------------------------------------------------------------------------
extern "C" void kernel_launch(void* const* d_in, const int* in_sizes, int n_in,
                              void* d_out, int out_size)
{
    (void)in_sizes; (void)n_in; (void)out_size;
    const float* x     = (const float*)d_in[0];
    const float* pos   = (const float*)d_in[1];
    const float* w_qkv = (const float*)d_in[2];
    const float* w_out = (const float*)d_in[3];
    const float* b_out = (const float*)d_in[4];
    float* out = (float*)d_out;

    float* qkv;
    __half *xh, *wqkvh, *wouth, *q, *k, *v, *attn;
    cudaGetSymbolAddress((void**)&qkv,   g_qkv);
    cudaGetSymbolAddress((void**)&xh,    g_xh);
    cudaGetSymbolAddress((void**)&wqkvh, g_wqkvh);
    cudaGetSymbolAddress((void**)&wouth, g_wouth);
    cudaGetSymbolAddress((void**)&q,     g_q);
    cudaGetSymbolAddress((void**)&k,     g_k);
    cudaGetSymbolAddress((void**)&v,     g_v);
    cudaGetSymbolAddress((void**)&attn,  g_attn);

    // 0) convert inputs to fp16
    {
        int n4x = M_ROWS * DIMc / 4;
        int n4w = DIMc * THREE_DIM / 4;
        int n4o = DIMc * DIMc / 4;
        tohalf<<<(n4x + 255) / 256, 256>>>((const float4*)x, (uint2*)xh, n4x);
        tohalf<<<(n4w + 255) / 256, 256>>>((const float4*)w_qkv, (uint2*)wqkvh, n4w);
        tohalf<<<(n4o + 255) / 256, 256>>>((const float4*)w_out, (uint2*)wouth, n4o);
    }
    // 1) QKV projection
    {
        dim3 grid(THREE_DIM / 128, M_ROWS / 128);
        gemm_f16<<<grid, 256>>>(xh, wqkvh, qkv, M_ROWS, THREE_DIM, DIMc, nullptr);
    }
    // 2) RoPE + scatter
    rope_scatter<<<512, 256>>>(qkv, pos, q, k, v);
    // 3) Flash attention (128q tiles, warp-local softmax)
    {
        dim3 grid(Nn / 128, Bc * Hh);
        flash_f16<<<grid, 256>>>(q, k, v, attn);
    }
    // 4) Output projection + bias
    {
        dim3 grid(DIMc / 128, M_ROWS / 128);
        gemm_f16<<<grid, 256>>>(attn, wouth, out, M_ROWS, DIMc, DIMc, b_out);
    }
}

// round 17
// speedup vs baseline: 1.0868x; 1.0003x over previous
#include <cuda_runtime.h>
#include <cuda_fp16.h>
#include <math.h>
#include <stdint.h>

// Problem constants
#define Bc 2
#define Nn 2048
#define DIMc 1024
#define Hh 16
#define HDc 64
#define Pp 2
#define M_ROWS (Bc * Nn)        // 4096
#define THREE_DIM (3 * DIMc)    // 3072

// Scratch (no cudaMalloc allowed)
__device__ __half g_qkvh[M_ROWS * THREE_DIM];      // fp16 qkv projection output
__device__ __half g_xh[M_ROWS * DIMc];             // fp16 x
__device__ __half g_wqkvh[DIMc * THREE_DIM];       // fp16 w_qkv
__device__ __half g_wouth[DIMc * DIMc];            // fp16 w_out
__device__ __half g_q[Bc * Hh * Nn * HDc];         // (b,h,n,d), q pre-scaled
__device__ __half g_k[Bc * Hh * Nn * HDc];
__device__ __half g_v[Bc * Hh * Nn * HDc];
__device__ __half g_attn[M_ROWS * DIMc];           // (b*n, h*HD)

// ---------------------------------------------------------------------------
// helpers
// ---------------------------------------------------------------------------
__device__ __forceinline__ float ex2(float x) {
    float r;
    asm("ex2.approx.ftz.f32 %0, %1;" : "=f"(r) : "f"(x));
    return r;
}
__device__ __forceinline__ void mma_f16(float d[4], const uint32_t a[4], const uint32_t b[2]) {
    asm volatile(
        "mma.sync.aligned.m16n8k16.row.col.f32.f16.f16.f32 "
        "{%0,%1,%2,%3}, {%4,%5,%6,%7}, {%8,%9}, {%0,%1,%2,%3};\n"
        : "+f"(d[0]), "+f"(d[1]), "+f"(d[2]), "+f"(d[3])
        : "r"(a[0]), "r"(a[1]), "r"(a[2]), "r"(a[3]), "r"(b[0]), "r"(b[1]));
}
__device__ __forceinline__ void ldm_x4(uint32_t r[4], uint32_t addr) {
    asm volatile("ldmatrix.sync.aligned.m8n8.x4.shared.b16 {%0,%1,%2,%3}, [%4];"
                 : "=r"(r[0]), "=r"(r[1]), "=r"(r[2]), "=r"(r[3]) : "r"(addr));
}
__device__ __forceinline__ void ldm_x2(uint32_t r[2], uint32_t addr) {
    asm volatile("ldmatrix.sync.aligned.m8n8.x2.shared.b16 {%0,%1}, [%2];"
                 : "=r"(r[0]), "=r"(r[1]) : "r"(addr));
}
__device__ __forceinline__ void ldm_x2t(uint32_t r[2], uint32_t addr) {
    asm volatile("ldmatrix.sync.aligned.m8n8.x2.trans.shared.b16 {%0,%1}, [%2];"
                 : "=r"(r[0]), "=r"(r[1]) : "r"(addr));
}
__device__ __forceinline__ uint32_t s2u(const void* p) {
    return (uint32_t)__cvta_generic_to_shared(p);
}

// ---------------------------------------------------------------------------
// f32 -> f16 convert (vectorized)
// ---------------------------------------------------------------------------
__global__ __launch_bounds__(256) void tohalf(
    const float4* __restrict__ src, uint2* __restrict__ dst, int n4)
{
    int i = blockIdx.x * blockDim.x + threadIdx.x;
    if (i < n4) {
        float4 v = src[i];
        __half2 h0 = __floats2half2_rn(v.x, v.y);
        __half2 h1 = __floats2half2_rn(v.z, v.w);
        uint2 o;
        o.x = *reinterpret_cast<uint32_t*>(&h0);
        o.y = *reinterpret_cast<uint32_t*>(&h1);
        dst[i] = o;
    }
}

// ---------------------------------------------------------------------------
// fp16 tensor-core GEMM (R16 mainloop, templated output type):
// 256 threads = 8 warps (2x4), CTA 128x128, warp 64x32, BK=32,
// single barrier per k-tile. OutT = float (with bias) or __half.
// ---------------------------------------------------------------------------
#define AP 40     // As pitch (halfs): 32 + 8
#define BP 136    // Bs pitch (halfs): 128 + 8

template <typename OutT>
__global__ __launch_bounds__(256) void gemm_f16(
    const __half* __restrict__ A, const __half* __restrict__ B,
    OutT* __restrict__ C, int M, int N, int K,
    const float* __restrict__ bias)
{
    __shared__ __half As[2][128 * AP];   // [m][k]
    __shared__ __half Bs[2][32 * BP];    // [k][n]

    int tid = threadIdx.x, lane = tid & 31, warp = tid >> 5;
    int wm = (warp >> 2) * 64, wn = (warp & 3) * 32;
    int rb = blockIdx.y * 128, cb = blockIdx.x * 128;

    int ar = tid >> 1, ac = (tid & 1) * 16;
    int br = tid >> 3, bc = (tid & 7) * 16;
    const __half* Ap = A + (size_t)(rb + ar) * K + ac;
    const __half* Bp = B + (size_t)br * N + cb + bc;

    uint4 ast[2], bst[2];
#pragma unroll
    for (int j = 0; j < 2; j++) {
        ast[j] = *(const uint4*)(Ap + j * 8);
        bst[j] = *(const uint4*)(Bp + j * 8);
    }
#pragma unroll
    for (int j = 0; j < 2; j++) {
        *(uint4*)&As[0][ar * AP + ac + j * 8] = ast[j];
        *(uint4*)&Bs[0][br * BP + bc + j * 8] = bst[j];
    }
    {
        const __half* Ap2 = Ap + 32;
        const __half* Bp2 = Bp + (size_t)32 * N;
#pragma unroll
        for (int j = 0; j < 2; j++) {
            ast[j] = *(const uint4*)(Ap2 + j * 8);
            bst[j] = *(const uint4*)(Bp2 + j * 8);
        }
    }
    __syncthreads();

    float acc[4][4][4];
#pragma unroll
    for (int mt = 0; mt < 4; mt++)
#pragma unroll
        for (int nt = 0; nt < 4; nt++)
#pragma unroll
            for (int i = 0; i < 4; i++) acc[mt][nt][i] = 0.f;

    int nk = K / 32;
    for (int kt = 0; kt < nk; kt++) {
        int s = kt & 1;
        if (kt + 1 < nk) {
            int s2 = s ^ 1;
#pragma unroll
            for (int j = 0; j < 2; j++) {
                *(uint4*)&As[s2][ar * AP + ac + j * 8] = ast[j];
                *(uint4*)&Bs[s2][br * BP + bc + j * 8] = bst[j];
            }
        }
        if (kt + 2 < nk) {
            const __half* Ap2 = Ap + (kt + 2) * 32;
            const __half* Bp2 = Bp + (size_t)(kt + 2) * 32 * N;
#pragma unroll
            for (int j = 0; j < 2; j++) {
                ast[j] = *(const uint4*)(Ap2 + j * 8);
                bst[j] = *(const uint4*)(Bp2 + j * 8);
            }
        }
        uint32_t asb = s2u(&As[s][0]);
        uint32_t bsb = s2u(&Bs[s][0]);
#pragma unroll
        for (int ks = 0; ks < 2; ks++) {
            uint32_t afr[4][4], bfr[4][2];
#pragma unroll
            for (int mt = 0; mt < 4; mt++) {
                int row = wm + mt * 16 + (lane & 15);
                int col = ks * 16 + ((lane >> 4) << 3);
                ldm_x4(afr[mt], asb + (row * AP + col) * 2);
            }
#pragma unroll
            for (int nt = 0; nt < 4; nt++) {
                int row = ks * 16 + (lane & 15);
                int col = wn + nt * 8;
                ldm_x2t(bfr[nt], bsb + (row * BP + col) * 2);
            }
#pragma unroll
            for (int mt = 0; mt < 4; mt++)
#pragma unroll
                for (int nt = 0; nt < 4; nt++)
                    mma_f16(acc[mt][nt], afr[mt], bfr[nt]);
        }
        __syncthreads();
    }

#pragma unroll
    for (int mt = 0; mt < 4; mt++) {
        int r0 = rb + wm + mt * 16 + (lane >> 2);
#pragma unroll
        for (int nt = 0; nt < 4; nt++) {
            int c0 = cb + wn + nt * 8 + 2 * (lane & 3);
            float bx = 0.f, by = 0.f;
            if (bias) { bx = bias[c0]; by = bias[c0 + 1]; }
            if constexpr (sizeof(OutT) == 4) {
                float2 o0 = make_float2(acc[mt][nt][0] + bx, acc[mt][nt][1] + by);
                float2 o1 = make_float2(acc[mt][nt][2] + bx, acc[mt][nt][3] + by);
                *(float2*)&C[(size_t)r0 * N + c0] = o0;
                *(float2*)&C[(size_t)(r0 + 8) * N + c0] = o1;
            } else {
                __half2 o0 = __floats2half2_rn(acc[mt][nt][0] + bx, acc[mt][nt][1] + by);
                __half2 o1 = __floats2half2_rn(acc[mt][nt][2] + bx, acc[mt][nt][3] + by);
                *(__half2*)&C[(size_t)r0 * N + c0] = o0;
                *(__half2*)&C[(size_t)(r0 + 8) * N + c0] = o1;
            }
        }
    }
}

// ---------------------------------------------------------------------------
// Axial RoPE + scatter, vectorized; reads fp16 qkv. 2 (b,n) rows per block
// iteration; each thread owns one (h, d-quad), q+k+v.
// ---------------------------------------------------------------------------
__global__ __launch_bounds__(256) void rope_scatter(
    const __half* __restrict__ qkv, const float* __restrict__ pos,
    __half* __restrict__ qo, __half* __restrict__ ko, __half* __restrict__ vo)
{
    const float SC = 0.125f * 1.44269504f;
    __shared__ float cs[2][32], sn[2][32];
    int t = threadIdx.x;
    int bnl = t >> 7;
    int item = t & 127;
    int h = item >> 3, j = item & 7;
    int d0 = j * 4;

    for (int bn0 = blockIdx.x * 2; bn0 < M_ROWS; bn0 += gridDim.x * 2) {
        if (t < 64) {
            int bl = t >> 5, u = t & 31;
            int p = u >> 4, i = u & 15;
            float freq = expf(-(float)i * (9.210340371976184f / 16.f));
            float th = pos[(size_t)(bn0 + bl) * Pp + p] * freq;
            float s, c;
            sincosf(th, &s, &c);
            cs[bl][u] = c;
            sn[bl][u] = s;
        }
        __syncthreads();

        int bn = bn0 + bnl;
        int b = bn / Nn, n = bn % Nn;
        const __half* base = qkv + (size_t)bn * THREE_DIM;
        size_t off = ((size_t)(b * Hh + h) * Nn + n) * HDc;

        float c0v = cs[bnl][d0],     s0v = sn[bnl][d0];
        float c1v = cs[bnl][d0 + 1], s1v = sn[bnl][d0 + 1];
        float c2v = cs[bnl][d0 + 2], s2v = sn[bnl][d0 + 2];
        float c3v = cs[bnl][d0 + 3], s3v = sn[bnl][d0 + 3];

        // q
        {
            uint2 r1 = *(const uint2*)(base + h * HDc + d0);
            uint2 r2 = *(const uint2*)(base + h * HDc + 32 + d0);
            float2 a0 = __half22float2(*(__half2*)&r1.x);
            float2 a1 = __half22float2(*(__half2*)&r1.y);
            float2 b0 = __half22float2(*(__half2*)&r2.x);
            float2 b1 = __half22float2(*(__half2*)&r2.y);
            __half2 lo0 = __floats2half2_rn((a0.x * c0v - b0.x * s0v) * SC,
                                            (a0.y * c1v - b0.y * s1v) * SC);
            __half2 lo1 = __floats2half2_rn((a1.x * c2v - b1.x * s2v) * SC,
                                            (a1.y * c3v - b1.y * s3v) * SC);
            __half2 hi0 = __floats2half2_rn((a0.x * s0v + b0.x * c0v) * SC,
                                            (a0.y * s1v + b0.y * c1v) * SC);
            __half2 hi1 = __floats2half2_rn((a1.x * s2v + b1.x * c2v) * SC,
                                            (a1.y * s3v + b1.y * c3v) * SC);
            uint2 olo, ohi;
            olo.x = *(uint32_t*)&lo0; olo.y = *(uint32_t*)&lo1;
            ohi.x = *(uint32_t*)&hi0; ohi.y = *(uint32_t*)&hi1;
            *(uint2*)(qo + off + d0) = olo;
            *(uint2*)(qo + off + 32 + d0) = ohi;
        }
        // k
        {
            uint2 r1 = *(const uint2*)(base + DIMc + h * HDc + d0);
            uint2 r2 = *(const uint2*)(base + DIMc + h * HDc + 32 + d0);
            float2 a0 = __half22float2(*(__half2*)&r1.x);
            float2 a1 = __half22float2(*(__half2*)&r1.y);
            float2 b0 = __half22float2(*(__half2*)&r2.x);
            float2 b1 = __half22float2(*(__half2*)&r2.y);
            __half2 lo0 = __floats2half2_rn(a0.x * c0v - b0.x * s0v,
                                            a0.y * c1v - b0.y * s1v);
            __half2 lo1 = __floats2half2_rn(a1.x * c2v - b1.x * s2v,
                                            a1.y * c3v - b1.y * s3v);
            __half2 hi0 = __floats2half2_rn(a0.x * s0v + b0.x * c0v,
                                            a0.y * s1v + b0.y * c1v);
            __half2 hi1 = __floats2half2_rn(a1.x * s2v + b1.x * c2v,
                                            a1.y * s3v + b1.y * c3v);
            uint2 olo, ohi;
            olo.x = *(uint32_t*)&lo0; olo.y = *(uint32_t*)&lo1;
            ohi.x = *(uint32_t*)&hi0; ohi.y = *(uint32_t*)&hi1;
            *(uint2*)(ko + off + d0) = olo;
            *(uint2*)(ko + off + 32 + d0) = ohi;
        }
        // v (straight fp16 copy)
        {
            uint2 r1 = *(const uint2*)(base + 2 * DIMc + h * HDc + d0);
            uint2 r2 = *(const uint2*)(base + 2 * DIMc + h * HDc + 32 + d0);
            *(uint2*)(vo + off + d0) = r1;
            *(uint2*)(vo + off + 32 + d0) = r2;
        }
        __syncthreads();
    }
}

// ---------------------------------------------------------------------------
// Flash attention (R16 version, unchanged): 256 threads, 128q x 64k tile,
// warp-local softmax (16-query strips), 2 barriers per tile.
// ---------------------------------------------------------------------------
#define QP 72   // half pitch: 64 + 8

__global__ __launch_bounds__(256) void flash_f16(
    const __half* __restrict__ Q, const __half* __restrict__ K,
    const __half* __restrict__ V, __half* __restrict__ O)
{
    __shared__ __half Qs[128 * QP];    // reused as Ps after Q frag hoist
    __shared__ __half Ks[64 * QP];
    __shared__ __half Vs[64 * QP];

    int tid = threadIdx.x, lane = tid & 31, warp = tid >> 5;
    int wm = warp * 16;                 // 16-query strip
    int bh = blockIdx.y, qt = blockIdx.x;
    int b = bh >> 4, h = bh & 15;

    const __half* Qb = Q + ((size_t)bh * Nn + qt * 128) * HDc;
    const __half* Kb = K + (size_t)bh * Nn * HDc;
    const __half* Vb = V + (size_t)bh * Nn * HDc;

    int lr = tid >> 1, lc = (tid & 1) * 32;
    {
        const __half* qg = Qb + (size_t)lr * HDc + lc;
#pragma unroll
        for (int j = 0; j < 4; j++)
            *(uint4*)&Qs[lr * QP + lc + j * 8] = *(const uint4*)(qg + j * 8);
    }
    __syncthreads();

    uint32_t qfr[4][4];
    {
        uint32_t qsb = s2u(&Qs[0]);
#pragma unroll
        for (int ks = 0; ks < 4; ks++) {
            int row = wm + (lane & 15);
            int col = ks * 16 + ((lane >> 4) << 3);
            ldm_x4(qfr[ks], qsb + (row * QP + col) * 2);
        }
    }
    __half* Ps = Qs;

    float accO[8][4];
#pragma unroll
    for (int nt = 0; nt < 8; nt++)
#pragma unroll
        for (int i = 0; i < 4; i++) accO[nt][i] = 0.f;
    float mA = -1e30f, mB = -1e30f, lA = 0.f, lB = 0.f;

    uint32_t ksb = s2u(&Ks[0]);
    uint32_t vsb = s2u(&Vs[0]);
    uint32_t psb = s2u(&Ps[0]);

    int kr = tid >> 2, kc = (tid & 3) * 16;
    int rA = wm + (lane >> 2), rB = rA + 8;

    for (int kt = 0; kt < Nn / 64; kt++) {
        {
            const __half* kg = Kb + ((size_t)(kt * 64 + kr)) * HDc + kc;
            const __half* vg = Vb + ((size_t)(kt * 64 + kr)) * HDc + kc;
#pragma unroll
            for (int j = 0; j < 2; j++) {
                *(uint4*)&Ks[kr * QP + kc + j * 8] = *(const uint4*)(kg + j * 8);
                *(uint4*)&Vs[kr * QP + kc + j * 8] = *(const uint4*)(vg + j * 8);
            }
        }
        __syncthreads();   // (1) tiles ready

        float s[8][4];
#pragma unroll
        for (int nt = 0; nt < 8; nt++)
#pragma unroll
            for (int i = 0; i < 4; i++) s[nt][i] = 0.f;
#pragma unroll
        for (int ks = 0; ks < 4; ks++) {
#pragma unroll
            for (int nt = 0; nt < 8; nt++) {
                int row = nt * 8 + (lane & 7);
                int col = ks * 16 + ((lane >> 3) & 1) * 8;
                uint32_t bfr[2];
                ldm_x2(bfr, ksb + (row * QP + col) * 2);
                mma_f16(s[nt], qfr[ks], bfr);
            }
        }

        float ma = -1e30f, mb = -1e30f;
#pragma unroll
        for (int nt = 0; nt < 8; nt++) {
            ma = fmaxf(ma, fmaxf(s[nt][0], s[nt][1]));
            mb = fmaxf(mb, fmaxf(s[nt][2], s[nt][3]));
        }
        ma = fmaxf(ma, __shfl_xor_sync(0xffffffffu, ma, 1));
        ma = fmaxf(ma, __shfl_xor_sync(0xffffffffu, ma, 2));
        mb = fmaxf(mb, __shfl_xor_sync(0xffffffffu, mb, 1));
        mb = fmaxf(mb, __shfl_xor_sync(0xffffffffu, mb, 2));

        float mnA = fmaxf(mA, ma), mnB = fmaxf(mB, mb);
        float fA = ex2(mA - mnA), fB = ex2(mB - mnB);

        float sa = 0.f, sb = 0.f;
#pragma unroll
        for (int nt = 0; nt < 8; nt++) {
            float p0 = ex2(s[nt][0] - mnA);
            float p1 = ex2(s[nt][1] - mnA);
            float p2 = ex2(s[nt][2] - mnB);
            float p3 = ex2(s[nt][3] - mnB);
            sa += p0 + p1;
            sb += p2 + p3;
            int c0 = nt * 8 + 2 * (lane & 3);
            *(__half2*)&Ps[rA * QP + c0] = __floats2half2_rn(p0, p1);
            *(__half2*)&Ps[rB * QP + c0] = __floats2half2_rn(p2, p3);
        }
        sa += __shfl_xor_sync(0xffffffffu, sa, 1);
        sa += __shfl_xor_sync(0xffffffffu, sa, 2);
        sb += __shfl_xor_sync(0xffffffffu, sb, 1);
        sb += __shfl_xor_sync(0xffffffffu, sb, 2);
        lA = lA * fA + sa;
        lB = lB * fB + sb;
        mA = mnA;
        mB = mnB;

#pragma unroll
        for (int nt = 0; nt < 8; nt++) {
            accO[nt][0] *= fA;
            accO[nt][1] *= fA;
            accO[nt][2] *= fB;
            accO[nt][3] *= fB;
        }
        __syncwarp();      // order P stores before own-warp ldmatrix

#pragma unroll
        for (int ks = 0; ks < 4; ks++) {
            uint32_t afr[4];
            {
                int row = wm + (lane & 15);
                int col = ks * 16 + ((lane >> 4) << 3);
                ldm_x4(afr, psb + (row * QP + col) * 2);
            }
#pragma unroll
            for (int nt = 0; nt < 8; nt++) {
                int row = ks * 16 + (lane & 15);
                int col = nt * 8;
                uint32_t bfr[2];
                ldm_x2t(bfr, vsb + (row * QP + col) * 2);
                mma_f16(accO[nt], afr, bfr);
            }
        }
        __syncthreads();   // (2) all K/V reads done before next overwrite
    }

    float ia = 1.f / lA, ib = 1.f / lB;
    size_t rowA = ((size_t)(b * Nn + qt * 128 + rA)) * DIMc + h * HDc;
    size_t rowB = ((size_t)(b * Nn + qt * 128 + rB)) * DIMc + h * HDc;
#pragma unroll
    for (int nt = 0; nt < 8; nt++) {
        int c0 = nt * 8 + 2 * (lane & 3);
        *(__half2*)&O[rowA + c0] = __floats2half2_rn(accO[nt][0] * ia, accO[nt][1] * ia);
        *(__half2*)&O[rowB + c0] = __floats2half2_rn(accO[nt][2] * ib, accO[nt][3] * ib);
    }
}

// ---------------------------------------------------------------------------
extern "C" void kernel_launch(void* const* d_in, const int* in_sizes, int n_in,
                              void* d_out, int out_size)
{
    (void)in_sizes; (void)n_in; (void)out_size;
    const float* x     = (const float*)d_in[0];
    const float* pos   = (const float*)d_in[1];
    const float* w_qkv = (const float*)d_in[2];
    const float* w_out = (const float*)d_in[3];
    const float* b_out = (const float*)d_in[4];
    float* out = (float*)d_out;

    __half *qkvh, *xh, *wqkvh, *wouth, *q, *k, *v, *attn;
    cudaGetSymbolAddress((void**)&qkvh,  g_qkvh);
    cudaGetSymbolAddress((void**)&xh,    g_xh);
    cudaGetSymbolAddress((void**)&wqkvh, g_wqkvh);
    cudaGetSymbolAddress((void**)&wouth, g_wouth);
    cudaGetSymbolAddress((void**)&q,     g_q);
    cudaGetSymbolAddress((void**)&k,     g_k);
    cudaGetSymbolAddress((void**)&v,     g_v);
    cudaGetSymbolAddress((void**)&attn,  g_attn);

    // 0) convert inputs to fp16
    {
        int n4x = M_ROWS * DIMc / 4;
        int n4w = DIMc * THREE_DIM / 4;
        int n4o = DIMc * DIMc / 4;
        tohalf<<<(n4x + 255) / 256, 256>>>((const float4*)x, (uint2*)xh, n4x);
        tohalf<<<(n4w + 255) / 256, 256>>>((const float4*)w_qkv, (uint2*)wqkvh, n4w);
        tohalf<<<(n4o + 255) / 256, 256>>>((const float4*)w_out, (uint2*)wouth, n4o);
    }
    // 1) QKV projection -> fp16 output
    {
        dim3 grid(THREE_DIM / 128, M_ROWS / 128);
        gemm_f16<__half><<<grid, 256>>>(xh, wqkvh, qkvh, M_ROWS, THREE_DIM, DIMc, nullptr);
    }
    // 2) RoPE + scatter (fp16 in/out)
    rope_scatter<<<512, 256>>>(qkvh, pos, q, k, v);
    // 3) Flash attention (128q tiles, warp-local softmax)
    {
        dim3 grid(Nn / 128, Bc * Hh);
        flash_f16<<<grid, 256>>>(q, k, v, attn);
    }
    // 4) Output projection + bias -> f32
    {
        dim3 grid(DIMc / 128, M_ROWS / 128);
        gemm_f16<float><<<grid, 256>>>(attn, wouth, out, M_ROWS, DIMc, DIMc, b_out);
    }
}